// round 15
// baseline (speedup 1.0000x reference)
#include <cuda_runtime.h>
#include <cuda_fp16.h>
#include <cstdint>
#include <cstddef>

// ============================================================
// out[16384,4096] = X[16384,4096] @ W[4096,4096]^T
// W = (w_pos>0) - (w_neg>0) in {-1,0,+1}
// R14 + split-CTA pipelines: warps 0-3 (A rows 0-63) and 4-7 (rows
// 64-127) share NO data -> each half gets its own A-stage ring and
// its own bar.sync id,128. Prefetch + W loads issued BEFORE the
// barrier (stage reused was idle for 2 iters; skew<1 iter => safe).
// B via PRMT selector expansion (no smem).
// ============================================================
#define M_TOTAL 16384
#define N_TOTAL 4096
#define K_TOTAL 4096

#define TILE_M 128
#define TILE_N 128
#define TILE_K 64
#define STAGES 4
#define NCHUNK (K_TOTAL / TILE_K)         // 64
#define N_TILES (N_TOTAL / TILE_N)        // 32
#define M_TILES (M_TOTAL / TILE_M)        // 128

#define HSTAGE_BYTES (64 * 128)           // 8192: 64 A-rows per half
#define HREGION (STAGES * HSTAGE_BYTES)   // 32768 per half
#define SMEM_TOTAL (2 * HREGION)          // 65536

// fp16 LUT for PRMT: code c in {0,1,2} -> fp16(c-1) bytes {0xBC,0x00,0x3C,0x00}
#define B_LUT 0x003C00BCu

__device__ __align__(128) __half   g_X[(size_t)M_TOTAL * K_TOTAL];   // 128 MB
// Selector table: word = blk*8192 + kword*32 + lane
//   blk = n>>3, kword = k/16 (0..255), lane = (n&7)*4 + t
#define W2_WORDS ((size_t)(N_TOTAL / 8) * (K_TOTAL / 16) * 32)       // 4194304
__device__ __align__(128) uint32_t g_W2[W2_WORDS];                   // 16 MB

// ============================================================
// PTX helpers (base ISA)
// ============================================================
__device__ __forceinline__ uint32_t smem_u32(const void* p) {
    uint32_t a;
    asm("{ .reg .u64 t; cvta.to.shared.u64 t, %1; cvt.u32.u64 %0, t; }"
        : "=r"(a) : "l"(p));
    return a;
}

#define CP_ASYNC16(dst_u32, src_ptr) \
    asm volatile("cp.async.cg.shared.global [%0], [%1], 16;" \
                 :: "r"(dst_u32), "l"(src_ptr) : "memory")
#define CP_COMMIT() asm volatile("cp.async.commit_group;" ::: "memory")
#define CP_WAIT(n)  asm volatile("cp.async.wait_group %0;" :: "n"(n) : "memory")

#define HBAR_SYNC(id) \
    asm volatile("bar.sync %0, 128;" :: "r"(id) : "memory")

__device__ __forceinline__ void ldsm4(uint32_t* r, uint32_t addr) {
    asm volatile("ldmatrix.sync.aligned.m8n8.x4.shared.b16 {%0,%1,%2,%3}, [%4];"
                 : "=r"(r[0]), "=r"(r[1]), "=r"(r[2]), "=r"(r[3]) : "r"(addr));
}

__device__ __forceinline__ void mma16816(float* d, const uint32_t* a,
                                         uint32_t b0, uint32_t b1) {
    asm volatile(
        "mma.sync.aligned.m16n8k16.row.col.f32.f16.f16.f32 "
        "{%0,%1,%2,%3}, {%4,%5,%6,%7}, {%8,%9}, {%0,%1,%2,%3};"
        : "+f"(d[0]), "+f"(d[1]), "+f"(d[2]), "+f"(d[3])
        : "r"(a[0]), "r"(a[1]), "r"(a[2]), "r"(a[3]), "r"(b0), "r"(b1));
}

__device__ __forceinline__ uint32_t prmt_lut(uint32_t sel) {
    uint32_t d;
    asm("prmt.b32 %0, %1, %2, %3;" : "=r"(d) : "r"(B_LUT), "r"(0u), "r"(sel));
    return d;
}

__device__ __forceinline__ uint32_t sw128(uint32_t off) {
    return off ^ ((off >> 3) & 0x70u);
}

// ============================================================
// Merged prep: blocks [0,XB) convert x->fp16; [XB,XB+W2B) build table
// ============================================================
#define N4X ((M_TOTAL * K_TOTAL) / 4)     // 16777216
#define XB  (N4X / 256)                   // 65536
#define W2B ((int)(W2_WORDS / 256))       // 16384

__global__ void k_prep(const float4* __restrict__ x,
                       const float* __restrict__ wp,
                       const float* __restrict__ wn) {
    int bi = blockIdx.x;
    if (bi < XB) {
        int i = bi * 256 + threadIdx.x;
        float4 v = x[i];
        __half2* dst = (__half2*)g_X;
        dst[2 * i + 0] = __floats2half2_rn(v.x, v.y);
        dst[2 * i + 1] = __floats2half2_rn(v.z, v.w);
    } else {
        int id = (bi - XB) * 256 + threadIdx.x;   // u32 index into g_W2
        int s     = id & 31;          // lane = (n&7)*4 + t
        int kword = (id >> 5) & 255;
        int blk   = id >> 13;
        int n  = blk * 8 + (s >> 2);
        int t  = s & 3;
        int kb = kword * 16 + t * 2;
        const float* wpr = wp + (size_t)n * K_TOTAL;
        const float* wnr = wn + (size_t)n * K_TOTAL;
        uint32_t c0 = (uint32_t)((wpr[kb + 0] > 0.f) - (wnr[kb + 0] > 0.f) + 1);
        uint32_t c1 = (uint32_t)((wpr[kb + 1] > 0.f) - (wnr[kb + 1] > 0.f) + 1);
        uint32_t c2 = (uint32_t)((wpr[kb + 8] > 0.f) - (wnr[kb + 8] > 0.f) + 1);
        uint32_t c3 = (uint32_t)((wpr[kb + 9] > 0.f) - (wnr[kb + 9] > 0.f) + 1);
        g_W2[id] = 0x03030303u | (c0 << 4) | (c1 << 12) | (c2 << 20) | (c3 << 28);
    }
}

// ============================================================
// GEMM
// ============================================================
// Per-half A stage fill: half h's 128 threads cover 64 rows x 128B.
// thread u (=tid&127) -> row u>>1, 4 x 16B at col (u&1)*64.
__device__ __forceinline__ void issue_tile_loads(
    uint32_t smem_base, int s, int kc, int m0, int tid)
{
    const int h   = tid >> 7;
    const int u   = tid & 127;
    const int row = u >> 1;
    const int c0  = (u & 1) * 4;
    uint32_t sa = smem_base + (uint32_t)h * HREGION + (uint32_t)s * HSTAGE_BYTES;
    const char* srcA = (const char*)(g_X + (size_t)(m0 + h * 64 + row) * K_TOTAL
                                     + kc * TILE_K);
    uint32_t rb = (uint32_t)row * 128u;
    #pragma unroll
    for (int c = 0; c < 4; c++) {
        uint32_t off = rb + (uint32_t)(c0 + c) * 16u;
        CP_ASYNC16(sa + sw128(off), srcA + (c0 + c) * 16);
    }
}

__global__ void __launch_bounds__(256, 2) plinear_gemm(float* __restrict__ out) {
    extern __shared__ char smem[];
    uint32_t smem_base = smem_u32(smem);
    const int tid = threadIdx.x;
    const int wid = tid >> 5;
    const int lid = tid & 31;
    const int h   = wid >> 2;            // half: warps 0-3 -> 0, 4-7 -> 1

    // N-fast: wave shares X tiles; W2 table (16MB) L2-resident
    const int nt = blockIdx.x & (N_TILES - 1);
    const int mt = blockIdx.x >> 5;
    const int m0 = mt * TILE_M;
    const int n0 = nt * TILE_N;

    // warp grid within half: 4 warps x (64M x 32N)
    const int mwarp = h * 64;
    const int nwarp = (wid & 3) * 32;

    float acc[4][4][4];
    #pragma unroll
    for (int i = 0; i < 4; i++)
        #pragma unroll
        for (int j = 0; j < 4; j++)
            #pragma unroll
            for (int c = 0; c < 4; c++) acc[i][j][c] = 0.f;

    // A ldmatrix offsets within an 8KB half-stage (64 rows x 128B),
    // pre-swizzled; XOR k-step advance (bits 5-6 only).
    const int a_r = (lid & 7) + (((lid >> 3) & 1) << 3);
    const int a_c = (lid >> 4) << 4;
    uint32_t aoff[4];
    #pragma unroll
    for (int i = 0; i < 4; i++)
        aoff[i] = sw128((uint32_t)(i * 16 + a_r) * 128u + a_c);

    const uint32_t hbase = smem_base + (uint32_t)h * HREGION;

    // W2 per-thread base: n-group d at +d*8192 words, kword kw at +kw*32.
    const uint32_t* wbase =
        g_W2 + (size_t)((n0 + nwarp) >> 3) * 8192 + lid;

    // Prologue: chunks 0,1 into stages 0,1 (prefetch distance 2)
    issue_tile_loads(smem_base, 0, 0, m0, tid); CP_COMMIT();
    issue_tile_loads(smem_base, 1, 1, m0, tid); CP_COMMIT();

    uint32_t a[2][4][4];
    uint32_t w[2][4];

    #pragma unroll 1
    for (int kc = 0; kc < NCHUNK; kc++) {
        const int s_cur = kc & (STAGES - 1);

        // W words for k-step 0 (no smem: safe before barrier)
        {
            const int kw = kc * 4;
            #pragma unroll
            for (int d = 0; d < 4; d++) w[0][d] = wbase[d * 8192 + kw * 32];
        }

        // Prefetch chunk kc+2 into stage (kc+2)&3 == (kc-2)&3 BEFORE the
        // barrier: that stage's reads finished at iter kc-2, and per-iter
        // barriers bound skew <1 iter, so no lagging reader remains.
        if (kc + 2 < NCHUNK)
            issue_tile_loads(smem_base, (kc + 2) & (STAGES - 1), kc + 2, m0, tid);
        CP_COMMIT();

        CP_WAIT(2);            // my chunk-kc group done (kc+1,kc+2 may pend)
        HBAR_SYNC(1 + h);      // half-scope: all 128 half-threads' fills done

        const uint32_t sa = hbase + (uint32_t)s_cur * HSTAGE_BYTES;

        // A k-step 0 fragments
        #pragma unroll
        for (int i = 0; i < 4; i++) ldsm4(a[0][i], sa + aoff[i]);

        #pragma unroll
        for (int ks = 0; ks < 4; ks++) {
            const int cur = ks & 1, nxt = cur ^ 1;
            if (ks < 3) {
                const int kw = kc * 4 + ks + 1;
                #pragma unroll
                for (int d = 0; d < 4; d++) w[nxt][d] = wbase[d * 8192 + kw * 32];
                const uint32_t kb = (uint32_t)(ks + 1) * 32u;  // bits 5-6 only
                #pragma unroll
                for (int i = 0; i < 4; i++) ldsm4(a[nxt][i], sa + (aoff[i] ^ kb));
            }
            // Expand B fragments: reg = prmt(LUT, sel16)
            uint32_t b[2][4];
            #pragma unroll
            for (int j = 0; j < 2; j++) {
                uint32_t w0 = w[cur][j * 2 + 0];
                uint32_t w1 = w[cur][j * 2 + 1];
                b[j][0] = prmt_lut(w0);
                b[j][1] = prmt_lut(w0 >> 16);
                b[j][2] = prmt_lut(w1);
                b[j][3] = prmt_lut(w1 >> 16);
            }
            #pragma unroll
            for (int i = 0; i < 4; i++)
                #pragma unroll
                for (int j = 0; j < 2; j++) {
                    mma16816(acc[i][2 * j + 0], a[cur][i], b[j][0], b[j][1]);
                    mma16816(acc[i][2 * j + 1], a[cur][i], b[j][2], b[j][3]);
                }
        }
    }

    // Epilogue
    {
        const int g  = lid >> 2;
        const int t2 = (lid & 3) * 2;
        #pragma unroll
        for (int i = 0; i < 4; i++) {
            float* r0 = out + (size_t)(m0 + mwarp + i * 16 + g) * N_TOTAL + n0 + nwarp + t2;
            float* r1 = r0 + 8 * N_TOTAL;
            #pragma unroll
            for (int j = 0; j < 4; j++) {
                *(float2*)(r0 + j * 8) = make_float2(acc[i][j][0], acc[i][j][1]);
                *(float2*)(r1 + j * 8) = make_float2(acc[i][j][2], acc[i][j][3]);
            }
        }
    }
}

// ============================================================
// Launch
// ============================================================
extern "C" void kernel_launch(void* const* d_in, const int* in_sizes, int n_in,
                              void* d_out, int out_size) {
    const float* x  = (const float*)d_in[0];
    const float* wp = (const float*)d_in[1];
    const float* wn = (const float*)d_in[2];
    float* out = (float*)d_out;

    cudaFuncSetAttribute(plinear_gemm,
                         cudaFuncAttributeMaxDynamicSharedMemorySize, SMEM_TOTAL);

    k_prep<<<XB + W2B, 256>>>((const float4*)x, wp, wn);
    plinear_gemm<<<M_TILES * N_TILES, 256, SMEM_TOTAL>>>(out);
}

// round 16
// speedup vs baseline: 1.0329x; 1.0329x over previous
#include <cuda_runtime.h>
#include <cuda_fp16.h>
#include <cstdint>
#include <cstddef>

// ============================================================
// out[16384,4096] = X[16384,4096] @ W[4096,4096]^T
// W = (w_pos>0) - (w_neg>0) in {-1,0,+1}
// R14 skeleton (best: 1391us) but B fragments PRE-EXPANDED to fp16 in
// prep: one uint4 LDG.128 per n-group per k-step IS the 4 B regs.
// Deletes 8 PRMT + selector shifts per k-step from the issue stream.
// A-only 4-stage cp.async pipeline; CTA 128x128, 8 warps 2x4,
// 2 CTAs/SM, 16 warps/SM.
// ============================================================
#define M_TOTAL 16384
#define N_TOTAL 4096
#define K_TOTAL 4096

#define TILE_M 128
#define TILE_N 128
#define TILE_K 64
#define STAGES 4
#define NCHUNK (K_TOTAL / TILE_K)         // 64
#define N_TILES (N_TOTAL / TILE_N)        // 32
#define M_TILES (M_TOTAL / TILE_M)        // 128

#define A_BYTES (TILE_M * TILE_K * 2)     // 16384 (A only)
#define STAGE_BYTES A_BYTES
#define SMEM_TOTAL (STAGES * STAGE_BYTES) // 65536

__device__ __align__(128) __half g_X[(size_t)M_TOTAL * K_TOTAL];     // 128 MB
// Pre-expanded B fragment table: uint4 index = (nb*256 + kw)*32 + lane
//   nb = n/16 (16-row block), kw = k/16 (0..255), lane = (n%8... see prep)
// uint4 = {row0 k(0,1), row0 k(8,9), row1 k(0,1), row1 k(8,9)} fp16x2 each,
// where row0 = nb*16 + (lane>>2), row1 = row0+8, k base = kw*16+(lane&3)*2.
// This is exactly the 4 B-operand regs of mma.m16n8k16 for that lane.
#define WF_QUADS ((size_t)(N_TOTAL / 16) * 256 * 32)                 // 2097152
__device__ __align__(128) uint4 g_WF[WF_QUADS];                      // 33.5 MB

// ============================================================
// PTX helpers (base ISA)
// ============================================================
__device__ __forceinline__ uint32_t smem_u32(const void* p) {
    uint32_t a;
    asm("{ .reg .u64 t; cvta.to.shared.u64 t, %1; cvt.u32.u64 %0, t; }"
        : "=r"(a) : "l"(p));
    return a;
}

#define CP_ASYNC16(dst_u32, src_ptr) \
    asm volatile("cp.async.cg.shared.global [%0], [%1], 16;" \
                 :: "r"(dst_u32), "l"(src_ptr) : "memory")
#define CP_COMMIT() asm volatile("cp.async.commit_group;" ::: "memory")
#define CP_WAIT(n)  asm volatile("cp.async.wait_group %0;" :: "n"(n) : "memory")

__device__ __forceinline__ void ldsm4(uint32_t* r, uint32_t addr) {
    asm volatile("ldmatrix.sync.aligned.m8n8.x4.shared.b16 {%0,%1,%2,%3}, [%4];"
                 : "=r"(r[0]), "=r"(r[1]), "=r"(r[2]), "=r"(r[3]) : "r"(addr));
}

__device__ __forceinline__ void mma16816(float* d, const uint32_t* a,
                                         uint32_t b0, uint32_t b1) {
    asm volatile(
        "mma.sync.aligned.m16n8k16.row.col.f32.f16.f16.f32 "
        "{%0,%1,%2,%3}, {%4,%5,%6,%7}, {%8,%9}, {%0,%1,%2,%3};"
        : "+f"(d[0]), "+f"(d[1]), "+f"(d[2]), "+f"(d[3])
        : "r"(a[0]), "r"(a[1]), "r"(a[2]), "r"(a[3]), "r"(b0), "r"(b1));
}

__device__ __forceinline__ uint32_t sw128(uint32_t off) {
    return off ^ ((off >> 3) & 0x70u);
}

// ============================================================
// Merged prep: blocks [0,XB) convert x->fp16; [XB,XB+WFB) build g_WF
// ============================================================
#define N4X ((M_TOTAL * K_TOTAL) / 4)     // 16777216
#define XB  (N4X / 256)                   // 65536
#define WFB ((int)(WF_QUADS / 256))       // 8192

__device__ __forceinline__ uint32_t tern_pair(
    const float* wpr, const float* wnr, int k)
{
    float v0 = (float)((wpr[k]     > 0.f) - (wnr[k]     > 0.f));
    float v1 = (float)((wpr[k + 1] > 0.f) - (wnr[k + 1] > 0.f));
    __half2 h = __floats2half2_rn(v0, v1);
    return *(uint32_t*)&h;
}

__global__ void k_prep(const float4* __restrict__ x,
                       const float* __restrict__ wp,
                       const float* __restrict__ wn) {
    int bi = blockIdx.x;
    if (bi < XB) {
        int i = bi * 256 + threadIdx.x;
        float4 v = x[i];
        __half2* dst = (__half2*)g_X;
        dst[2 * i + 0] = __floats2half2_rn(v.x, v.y);
        dst[2 * i + 1] = __floats2half2_rn(v.z, v.w);
    } else {
        int id = (bi - XB) * 256 + threadIdx.x;   // uint4 index into g_WF
        int lane = id & 31;
        int kw   = (id >> 5) & 255;
        int nb   = id >> 13;
        int t = lane & 3, r = lane >> 2;
        int row0 = nb * 16 + r;
        int row1 = row0 + 8;
        int k0 = kw * 16 + t * 2;
        const float* wp0 = wp + (size_t)row0 * K_TOTAL;
        const float* wn0 = wn + (size_t)row0 * K_TOTAL;
        const float* wp1 = wp + (size_t)row1 * K_TOTAL;
        const float* wn1 = wn + (size_t)row1 * K_TOTAL;
        uint4 u;
        u.x = tern_pair(wp0, wn0, k0);
        u.y = tern_pair(wp0, wn0, k0 + 8);
        u.z = tern_pair(wp1, wn1, k0);
        u.w = tern_pair(wp1, wn1, k0 + 8);
        g_WF[id] = u;
    }
}

// ============================================================
// GEMM
// ============================================================
// A-only stage fill (256 threads): thread t -> row t>>1, 4 x 16B.
__device__ __forceinline__ void issue_tile_loads(
    uint32_t smem_base, int s, int kc, int m0, int tid)
{
    uint32_t sa = smem_base + (uint32_t)s * STAGE_BYTES;
    const int row = tid >> 1;
    const int c0  = (tid & 1) * 4;
    const char* srcA = (const char*)(g_X + (size_t)(m0 + row) * K_TOTAL + kc * TILE_K);
    uint32_t rb = (uint32_t)row * 128u;
    #pragma unroll
    for (int c = 0; c < 4; c++) {
        uint32_t off = rb + (uint32_t)(c0 + c) * 16u;
        CP_ASYNC16(sa + sw128(off), srcA + (c0 + c) * 16);
    }
}

__global__ void __launch_bounds__(256, 2) plinear_gemm(float* __restrict__ out) {
    extern __shared__ char smem[];
    uint32_t smem_base = smem_u32(smem);
    const int tid = threadIdx.x;
    const int wid = tid >> 5;
    const int lid = tid & 31;

    // N-fast: wave shares X tiles; g_WF (33MB) L2-resident
    const int nt = blockIdx.x & (N_TILES - 1);
    const int mt = blockIdx.x >> 5;
    const int m0 = mt * TILE_M;
    const int n0 = nt * TILE_N;

    // warp grid 2(M) x 4(N): warp tile 64 x 32
    const int mwarp = (wid >> 2) * 64;
    const int nwarp = (wid & 3) * 32;

    float acc[4][4][4];
    #pragma unroll
    for (int i = 0; i < 4; i++)
        #pragma unroll
        for (int j = 0; j < 4; j++)
            #pragma unroll
            for (int c = 0; c < 4; c++) acc[i][j][c] = 0.f;

    // A ldmatrix base offsets (pre-swizzled); XOR k-step advance.
    const int a_r = (lid & 7) + (((lid >> 3) & 1) << 3);
    const int a_c = (lid >> 4) << 4;
    uint32_t aoff[4];
    #pragma unroll
    for (int i = 0; i < 4; i++)
        aoff[i] = sw128((uint32_t)(mwarp + i * 16 + a_r) * 128u + a_c);

    // B fragment table base: n-block j at +j*8192 quads, kword kw at +kw*32.
    const uint4* wfbase =
        g_WF + (size_t)((n0 + nwarp) >> 4) * 8192 + lid;

    // Prologue: A stages 0..2 (prefetch distance 3)
    issue_tile_loads(smem_base, 0, 0, m0, tid); CP_COMMIT();
    issue_tile_loads(smem_base, 1, 1, m0, tid); CP_COMMIT();
    issue_tile_loads(smem_base, 2, 2, m0, tid); CP_COMMIT();

    uint32_t a[2][4][4];
    uint4 bv[2][2];          // [pipeline][j]: 4 B regs per n-group

    #pragma unroll 1
    for (int kc = 0; kc < NCHUNK; kc++) {
        const int s_cur = kc & (STAGES - 1);

        // B fragments for k-step 0 of this chunk (no smem dependency)
        {
            const int kw = kc * 4;
            #pragma unroll
            for (int j = 0; j < 2; j++) bv[0][j] = wfbase[j * 8192 + kw * 32];
        }

        CP_WAIT(2);          // A stage kc arrived (2 newer groups may pend)
        __syncthreads();     // + prior reads of reused stage complete

        const int pf = kc + 3;
        if (pf < NCHUNK)
            issue_tile_loads(smem_base, pf & (STAGES - 1), pf, m0, tid);
        CP_COMMIT();

        const uint32_t sa = smem_base + (uint32_t)s_cur * STAGE_BYTES;

        // A k-step 0 fragments
        #pragma unroll
        for (int i = 0; i < 4; i++) ldsm4(a[0][i], sa + aoff[i]);

        #pragma unroll
        for (int ks = 0; ks < 4; ks++) {
            const int cur = ks & 1, nxt = cur ^ 1;
            if (ks < 3) {
                const int kw = kc * 4 + ks + 1;
                #pragma unroll
                for (int j = 0; j < 2; j++)
                    bv[nxt][j] = wfbase[j * 8192 + kw * 32];
                const uint32_t kb = (uint32_t)(ks + 1) * 32u;  // bits 5-6 only
                #pragma unroll
                for (int i = 0; i < 4; i++) ldsm4(a[nxt][i], sa + (aoff[i] ^ kb));
            }
            #pragma unroll
            for (int i = 0; i < 4; i++)
                #pragma unroll
                for (int j = 0; j < 2; j++) {
                    mma16816(acc[i][2 * j + 0], a[cur][i], bv[cur][j].x, bv[cur][j].y);
                    mma16816(acc[i][2 * j + 1], a[cur][i], bv[cur][j].z, bv[cur][j].w);
                }
        }
    }

    // Epilogue
    {
        const int g  = lid >> 2;
        const int t2 = (lid & 3) * 2;
        #pragma unroll
        for (int i = 0; i < 4; i++) {
            float* r0 = out + (size_t)(m0 + mwarp + i * 16 + g) * N_TOTAL + n0 + nwarp + t2;
            float* r1 = r0 + 8 * N_TOTAL;
            #pragma unroll
            for (int j = 0; j < 4; j++) {
                *(float2*)(r0 + j * 8) = make_float2(acc[i][j][0], acc[i][j][1]);
                *(float2*)(r1 + j * 8) = make_float2(acc[i][j][2], acc[i][j][3]);
            }
        }
    }
}

// ============================================================
// Launch
// ============================================================
extern "C" void kernel_launch(void* const* d_in, const int* in_sizes, int n_in,
                              void* d_out, int out_size) {
    const float* x  = (const float*)d_in[0];
    const float* wp = (const float*)d_in[1];
    const float* wn = (const float*)d_in[2];
    float* out = (float*)d_out;

    cudaFuncSetAttribute(plinear_gemm,
                         cudaFuncAttributeMaxDynamicSharedMemorySize, SMEM_TOTAL);

    k_prep<<<XB + WFB, 256>>>((const float4*)x, wp, wn);
    plinear_gemm<<<M_TILES * N_TILES, 256, SMEM_TOTAL>>>(out);
}